// round 9
// baseline (speedup 1.0000x reference)
#include <cuda_runtime.h>
#include <cuda_fp16.h>
#include <cstdint>

#define BATCH 16
#define HEADS 8
#define DH 32
#define LSP 1024
#define CIN 256
#define BH_N (BATCH*HEADS)
#define QT 128            // queries per CTA in attn (8 warps x 16)
#define KTL 128           // keys per tile
#define NKT (LSP/KTL)
#define KPAD 40           // K smem row stride (halves)
#define VPAD 136          // V smem row stride (halves)
#define XLT 256           // l-tile for qkv GEMM
#define XPAD 264          // Xs row stride (halves)
#define WPAD 40           // Ws row stride (halves)

// fp16 staging: q,k as [bh][l][d]; v as [bh][d][l]
__device__ __half g_qh[(size_t)BH_N * LSP * DH];
__device__ __half g_kh[(size_t)BH_N * LSP * DH];
__device__ __half g_vh[(size_t)BH_N * DH * LSP];
// sine positional encoding table [l][ch], f32 (batch-invariant)
__device__ float  g_pe[(size_t)LSP * CIN];

// ---------------------------------------------------------------------------
// HMMA / LDSM / cp.async helpers
// ---------------------------------------------------------------------------
__device__ __forceinline__ void mma16816(
    float& d0, float& d1, float& d2, float& d3,
    uint32_t a0, uint32_t a1, uint32_t a2, uint32_t a3,
    uint32_t b0, uint32_t b1)
{
    asm volatile(
        "mma.sync.aligned.m16n8k16.row.col.f32.f16.f16.f32 "
        "{%0,%1,%2,%3}, {%4,%5,%6,%7}, {%8,%9}, {%0,%1,%2,%3};"
        : "+f"(d0), "+f"(d1), "+f"(d2), "+f"(d3)
        : "r"(a0), "r"(a1), "r"(a2), "r"(a3), "r"(b0), "r"(b1));
}

__device__ __forceinline__ void ldsm_x4(uint32_t& r0, uint32_t& r1,
                                        uint32_t& r2, uint32_t& r3,
                                        const void* p)
{
    uint32_t a = (uint32_t)__cvta_generic_to_shared(p);
    asm volatile(
        "ldmatrix.sync.aligned.m8n8.x4.shared.b16 {%0,%1,%2,%3}, [%4];"
        : "=r"(r0), "=r"(r1), "=r"(r2), "=r"(r3) : "r"(a));
}

__device__ __forceinline__ void ldsm_x4_trans(uint32_t& r0, uint32_t& r1,
                                              uint32_t& r2, uint32_t& r3,
                                              const void* p)
{
    uint32_t a = (uint32_t)__cvta_generic_to_shared(p);
    asm volatile(
        "ldmatrix.sync.aligned.m8n8.x4.trans.shared.b16 {%0,%1,%2,%3}, [%4];"
        : "=r"(r0), "=r"(r1), "=r"(r2), "=r"(r3) : "r"(a));
}

__device__ __forceinline__ void cp16(void* smem, const void* gmem)
{
    uint32_t a = (uint32_t)__cvta_generic_to_shared(smem);
    asm volatile("cp.async.cg.shared.global [%0], [%1], 16;"
                 :: "r"(a), "l"(gmem));
}

__device__ __forceinline__ uint32_t exp2_f16x2(float t0, float t1)
{
    uint32_t p;
    asm("cvt.rn.f16x2.f32 %0, %1, %2;" : "=r"(p) : "f"(t1), "f"(t0));
    asm("ex2.approx.f16x2 %0, %0;" : "+r"(p));
    return p;
}

// ---------------------------------------------------------------------------
// Kernel 0: fill PE table (batch-invariant). 262144 elems.
// ---------------------------------------------------------------------------
__global__ __launch_bounds__(256) void pe_kernel()
{
    const int idx = blockIdx.x * 256 + threadIdx.x;
    const int l  = idx >> 8;
    const int ch = idx & 255;
    const float div = __expf(-0.03597789207803197f * (float)(ch & ~1));
    float sv, cv;
    __sincosf(div * (float)l, &sv, &cv);
    g_pe[idx] = (ch & 1) ? cv : sv;
}

// ---------------------------------------------------------------------------
// Kernel 1: grouped 1x1 conv as HMMA GEMM. CTA = (l-tile 256, bh).
// Out[l][o] = sum_c X[c][l] * W[o][c] ; PE (table) fused into K epilogue.
// ---------------------------------------------------------------------------
__global__ __launch_bounds__(256) void qkv_kernel(
    const float* __restrict__ x,
    const float* __restrict__ wq,
    const float* __restrict__ wk,
    const float* __restrict__ wv)
{
    __shared__ __half Xs[32][XPAD];      // [c][l]
    __shared__ __half Ws[3][32][WPAD];   // [mat][o][c]

    const int l0  = blockIdx.x * XLT;
    const int bh  = blockIdx.y;
    const int b   = bh >> 3;
    const int h   = bh & 7;
    const int tid = threadIdx.x;
    const int wid = tid >> 5;
    const int lane = tid & 31;
    const int gid = lane >> 2;
    const int tig = lane & 3;

    // stage x tile [32 c][256 l] as fp16
    for (int idx = tid; idx < 32 * 64; idx += 256) {
        const int c  = idx >> 6;
        const int l4 = (idx & 63) * 4;
        const float4 v = *(const float4*)(x +
            ((size_t)(b * CIN + h * 32 + c) * LSP) + l0 + l4);
        __half2 h0 = __floats2half2_rn(v.x, v.y);
        __half2 h1 = __floats2half2_rn(v.z, v.w);
        *(__half2*)&Xs[c][l4]     = h0;
        *(__half2*)&Xs[c][l4 + 2] = h1;
    }
    // stage weights (3 x 32x32) as fp16
    {
        const float* wp[3] = {wq, wk, wv};
        for (int idx = tid; idx < 3072; idx += 256) {
            const int mat = idx >> 10;
            const int o   = (idx >> 5) & 31;
            const int c   = idx & 31;
            Ws[mat][o][c] = __float2half(wp[mat][(h * 32 + o) * 32 + c]);
        }
    }
    __syncthreads();

    const int krow = lane & 7;
    const int kcol = ((lane >> 3) & 3) * 8;
    const int arow_g = ((lane >> 4) << 3) + (lane & 7);
    const int acol_g = ((lane >> 3) & 1) * 8;

    const int m0 = wid * 32;

    #pragma unroll
    for (int mc = 0; mc < 2; mc++) {
        const int m = m0 + mc * 16;
        uint32_t a[2][4];
        #pragma unroll
        for (int ks = 0; ks < 2; ks++)
            ldsm_x4_trans(a[ks][0], a[ks][1], a[ks][2], a[ks][3],
                          &Xs[ks * 16 + arow_g][m + acol_g]);

        #pragma unroll
        for (int mat = 0; mat < 3; mat++) {
            #pragma unroll
            for (int nc = 0; nc < 4; nc++) {
                uint32_t b0, b1, b2, b3;
                ldsm_x4(b0, b1, b2, b3, &Ws[mat][nc * 8 + krow][kcol]);
                float d0 = 0.f, d1 = 0.f, d2 = 0.f, d3 = 0.f;
                mma16816(d0, d1, d2, d3,
                         a[0][0], a[0][1], a[0][2], a[0][3], b0, b1);
                mma16816(d0, d1, d2, d3,
                         a[1][0], a[1][1], a[1][2], a[1][3], b2, b3);

                const int lrow = l0 + m + gid;      // fragment rows: lrow, lrow+8
                const int dch  = nc * 8 + tig * 2;  // cols: dch, dch+1

                if (mat == 0) {
                    __half2 v0 = __floats2half2_rn(d0, d1);
                    __half2 v1 = __floats2half2_rn(d2, d3);
                    *(__half2*)(g_qh + ((size_t)bh * LSP + lrow)     * DH + dch) = v0;
                    *(__half2*)(g_qh + ((size_t)bh * LSP + lrow + 8) * DH + dch) = v1;
                } else if (mat == 1) {
                    const int gch = h * 32 + dch;
                    const float2 p0 = *(const float2*)(g_pe + (size_t)lrow * CIN + gch);
                    const float2 p1 = *(const float2*)(g_pe + (size_t)(lrow + 8) * CIN + gch);
                    __half2 v0 = __floats2half2_rn(d0 + p0.x, d1 + p0.y);
                    __half2 v1 = __floats2half2_rn(d2 + p1.x, d3 + p1.y);
                    *(__half2*)(g_kh + ((size_t)bh * LSP + lrow)     * DH + dch) = v0;
                    *(__half2*)(g_kh + ((size_t)bh * LSP + lrow + 8) * DH + dch) = v1;
                } else {
                    __half* vb = g_vh + (size_t)bh * DH * LSP;
                    vb[(size_t)(dch    ) * LSP + lrow    ] = __float2half(d0);
                    vb[(size_t)(dch + 1) * LSP + lrow    ] = __float2half(d1);
                    vb[(size_t)(dch    ) * LSP + lrow + 8] = __float2half(d2);
                    vb[(size_t)(dch + 1) * LSP + lrow + 8] = __float2half(d3);
                }
            }
        }
    }
}

// ---------------------------------------------------------------------------
// Kernel 2: register-fragment flash attention, HMMA + LDSM + cp.async.
// lsum scalar (off tensor pipe) with FINAL QUAD REDUCTION, tree max,
// interleaved PV accumulators.
// ---------------------------------------------------------------------------
__global__ __launch_bounds__(256, 2) void attn_kernel(float* __restrict__ out)
{
    __shared__ __half Ks[2][KTL][KPAD];   // [buf][key][d]
    __shared__ __half Vs[2][DH][VPAD];    // [buf][d][key]

    const int tid  = threadIdx.x;
    const int wid  = tid >> 5;
    const int lane = tid & 31;
    const int gid  = lane >> 2;
    const int tig  = lane & 3;
    const int bh   = blockIdx.y;
    const int q0   = blockIdx.x * QT + wid * 16;
    const float L2E = 1.4426950408889634f;

    const __half* kbase = g_kh + (size_t)bh * LSP * DH;
    const __half* vbase = g_vh + (size_t)bh * DH * LSP;

    const int kr = tid >> 1, kc = (tid & 1) * 16;
    const int vr0 = tid >> 4,         vc0 = (tid & 15) * 8;
    const int vr1 = (tid + 256) >> 4, vc1 = ((tid + 256) & 15) * 8;

    uint32_t qa[8];
    {
        const __half* qb = g_qh + ((size_t)bh * LSP + q0) * DH;
        #pragma unroll
        for (int kk = 0; kk < 2; kk++) {
            qa[kk*4+0] = *(const uint32_t*)(qb + (gid    ) * DH + kk*16     + tig*2);
            qa[kk*4+1] = *(const uint32_t*)(qb + (gid + 8) * DH + kk*16     + tig*2);
            qa[kk*4+2] = *(const uint32_t*)(qb + (gid    ) * DH + kk*16 + 8 + tig*2);
            qa[kk*4+3] = *(const uint32_t*)(qb + (gid + 8) * DH + kk*16 + 8 + tig*2);
        }
    }

    {
        cp16(&Ks[0][kr][kc],     kbase + (size_t)kr * DH + kc);
        cp16(&Ks[0][kr][kc + 8], kbase + (size_t)kr * DH + kc + 8);
        cp16(&Vs[0][vr0][vc0],   vbase + (size_t)vr0 * LSP + vc0);
        cp16(&Vs[0][vr1][vc1],   vbase + (size_t)vr1 * LSP + vc1);
        asm volatile("cp.async.commit_group;" ::: "memory");
    }

    float o[16];
    #pragma unroll
    for (int i = 0; i < 16; i++) o[i] = 0.f;
    float m0 = -1e30f, m1 = -1e30f, l0 = 0.f, l1 = 0.f;

    const int krow = lane & 7;
    const int kcol = ((lane >> 3) & 3) * 8;

    for (int kt = 0; kt < NKT; kt++) {
        const int buf = kt & 1;
        if (kt + 1 < NKT) {
            const size_t koff = (size_t)(kt + 1) * KTL;
            cp16(&Ks[buf^1][kr][kc],     kbase + (koff + kr) * DH + kc);
            cp16(&Ks[buf^1][kr][kc + 8], kbase + (koff + kr) * DH + kc + 8);
            cp16(&Vs[buf^1][vr0][vc0],   vbase + (size_t)vr0 * LSP + koff + vc0);
            cp16(&Vs[buf^1][vr1][vc1],   vbase + (size_t)vr1 * LSP + koff + vc1);
            asm volatile("cp.async.commit_group;" ::: "memory");
            asm volatile("cp.async.wait_group 1;" ::: "memory");
        } else {
            asm volatile("cp.async.wait_group 0;" ::: "memory");
        }
        __syncthreads();

        // ---- S = Q x K^T ----
        float s[16][4];
        #pragma unroll
        for (int j = 0; j < 16; j++) {
            uint32_t b0, b1, b2, b3;
            ldsm_x4(b0, b1, b2, b3, &Ks[buf][j * 8 + krow][kcol]);
            s[j][0] = s[j][1] = s[j][2] = s[j][3] = 0.f;
            mma16816(s[j][0], s[j][1], s[j][2], s[j][3],
                     qa[0], qa[1], qa[2], qa[3], b0, b1);
            mma16816(s[j][0], s[j][1], s[j][2], s[j][3],
                     qa[4], qa[5], qa[6], qa[7], b2, b3);
        }

        // ---- row max: tree reduction ----
        float r0[8], r1[8];
        #pragma unroll
        for (int j = 0; j < 8; j++) {
            r0[j] = fmaxf(fmaxf(s[2*j][0], s[2*j][1]),
                          fmaxf(s[2*j+1][0], s[2*j+1][1]));
            r1[j] = fmaxf(fmaxf(s[2*j][2], s[2*j][3]),
                          fmaxf(s[2*j+1][2], s[2*j+1][3]));
        }
        #pragma unroll
        for (int w = 4; w >= 1; w >>= 1) {
            #pragma unroll
            for (int j = 0; j < w; j++) {
                r0[j] = fmaxf(r0[j], r0[j + w]);
                r1[j] = fmaxf(r1[j], r1[j + w]);
            }
        }
        float nm0 = fmaxf(m0, r0[0]);
        float nm1 = fmaxf(m1, r1[0]);
        nm0 = fmaxf(nm0, __shfl_xor_sync(0xffffffffu, nm0, 1));
        nm0 = fmaxf(nm0, __shfl_xor_sync(0xffffffffu, nm0, 2));
        nm1 = fmaxf(nm1, __shfl_xor_sync(0xffffffffu, nm1, 1));
        nm1 = fmaxf(nm1, __shfl_xor_sync(0xffffffffu, nm1, 2));
        const float c0 = __expf(m0 - nm0);
        const float c1 = __expf(m1 - nm1);
        m0 = nm0; m1 = nm1;
        l0 *= c0;  l1 *= c1;
        #pragma unroll
        for (int nc = 0; nc < 4; nc++) {
            o[nc*4+0] *= c0; o[nc*4+1] *= c0;
            o[nc*4+2] *= c1; o[nc*4+3] *= c1;
        }

        // ---- P = exp2((s-m)*log2e), packed; per-thread partial lsum ----
        // (partial sums cover cols {tig*2,tig*2+1} per block; quad-reduced
        //  once after the tile loop — valid since m is quad-uniform)
        const float nb0 = -m0 * L2E;
        const float nb1 = -m1 * L2E;
        float lsA0 = 0.f, lsA1 = 0.f, lsB0 = 0.f, lsB1 = 0.f;
        #pragma unroll
        for (int j = 0; j < 16; j++) {
            float t00 = fmaf(s[j][0], L2E, nb0);
            float t01 = fmaf(s[j][1], L2E, nb0);
            float t10 = fmaf(s[j][2], L2E, nb1);
            float t11 = fmaf(s[j][3], L2E, nb1);
            uint32_t p0 = exp2_f16x2(t00, t01);
            uint32_t p1 = exp2_f16x2(t10, t11);
            s[j][0] = __uint_as_float(p0);
            s[j][1] = __uint_as_float(p1);
            float2 f0 = __half22float2(*(__half2*)&p0);
            float2 f1 = __half22float2(*(__half2*)&p1);
            if (j & 1) { lsA1 += f0.x + f0.y; lsB1 += f1.x + f1.y; }
            else       { lsA0 += f0.x + f0.y; lsB0 += f1.x + f1.y; }
        }
        l0 += lsA0 + lsA1;
        l1 += lsB0 + lsB1;

        // ---- O += P x V : cc outer so the 4 nc accumulators interleave ----
        #pragma unroll
        for (int cc = 0; cc < 4; cc++) {
            uint32_t v[4][4];
            #pragma unroll
            for (int nc = 0; nc < 4; nc++)
                ldsm_x4(v[nc][0], v[nc][1], v[nc][2], v[nc][3],
                        &Vs[buf][nc * 8 + krow][cc * 32 + kcol]);
            const int c = cc * 2;
            const uint32_t a00 = __float_as_uint(s[2*c    ][0]);
            const uint32_t a01 = __float_as_uint(s[2*c    ][1]);
            const uint32_t a02 = __float_as_uint(s[2*c + 1][0]);
            const uint32_t a03 = __float_as_uint(s[2*c + 1][1]);
            const uint32_t a10 = __float_as_uint(s[2*c + 2][0]);
            const uint32_t a11 = __float_as_uint(s[2*c + 2][1]);
            const uint32_t a12 = __float_as_uint(s[2*c + 3][0]);
            const uint32_t a13 = __float_as_uint(s[2*c + 3][1]);
            #pragma unroll
            for (int nc = 0; nc < 4; nc++)
                mma16816(o[nc*4+0], o[nc*4+1], o[nc*4+2], o[nc*4+3],
                         a00, a01, a02, a03, v[nc][0], v[nc][1]);
            #pragma unroll
            for (int nc = 0; nc < 4; nc++)
                mma16816(o[nc*4+0], o[nc*4+1], o[nc*4+2], o[nc*4+3],
                         a10, a11, a12, a13, v[nc][2], v[nc][3]);
        }
        __syncthreads();
    }

    // quad reduction of the partial row sums (cols were split across tig)
    l0 += __shfl_xor_sync(0xffffffffu, l0, 1);
    l0 += __shfl_xor_sync(0xffffffffu, l0, 2);
    l1 += __shfl_xor_sync(0xffffffffu, l1, 1);
    l1 += __shfl_xor_sync(0xffffffffu, l1, 2);

    const float inv0 = 1.0f / l0;
    const float inv1 = 1.0f / l1;

    float* ob = out + (size_t)bh * DH * LSP;
    #pragma unroll
    for (int nc = 0; nc < 4; nc++) {
        const int d = nc * 8 + tig * 2;
        ob[(size_t)(d    ) * LSP + q0 + gid    ] = o[nc*4+0] * inv0;
        ob[(size_t)(d + 1) * LSP + q0 + gid    ] = o[nc*4+1] * inv0;
        ob[(size_t)(d    ) * LSP + q0 + gid + 8] = o[nc*4+2] * inv1;
        ob[(size_t)(d + 1) * LSP + q0 + gid + 8] = o[nc*4+3] * inv1;
    }
}

// ---------------------------------------------------------------------------
extern "C" void kernel_launch(void* const* d_in, const int* in_sizes, int n_in,
                              void* d_out, int out_size)
{
    const float* x  = (const float*)d_in[0];
    const float* wq = (const float*)d_in[1];
    const float* wk = (const float*)d_in[2];
    const float* wv = (const float*)d_in[3];
    float* out = (float*)d_out;

    pe_kernel<<<LSP * CIN / 256, 256>>>();

    dim3 g1(LSP / XLT, BH_N);
    qkv_kernel<<<g1, 256>>>(x, wq, wk, wv);

    dim3 g2(LSP / QT, BH_N);
    attn_kernel<<<g2, 256>>>(out);
}

// round 10
// speedup vs baseline: 1.0665x; 1.0665x over previous
#include <cuda_runtime.h>
#include <cuda_fp16.h>
#include <cstdint>

#define BATCH 16
#define HEADS 8
#define DH 32
#define LSP 1024
#define CIN 256
#define BH_N (BATCH*HEADS)
#define QT 128            // queries per CTA in attn (8 warps x 16)
#define KTL 128           // keys per tile
#define NKT (LSP/KTL)
#define KPAD 40           // K smem row stride (halves)
#define VPAD 136          // V smem row stride (halves)
#define XLT 256           // l-tile for qkv GEMM
#define XPAD 264          // Xs row stride (halves)
#define WPAD 40           // Ws row stride (halves)

// fp16 staging: q,k as [bh][l][d]; v as [bh][d][l]
__device__ __half g_qh[(size_t)BH_N * LSP * DH];
__device__ __half g_kh[(size_t)BH_N * LSP * DH];
__device__ __half g_vh[(size_t)BH_N * DH * LSP];

// ---------------------------------------------------------------------------
// HMMA / LDSM / cp.async helpers
// ---------------------------------------------------------------------------
__device__ __forceinline__ void mma16816(
    float& d0, float& d1, float& d2, float& d3,
    uint32_t a0, uint32_t a1, uint32_t a2, uint32_t a3,
    uint32_t b0, uint32_t b1)
{
    asm volatile(
        "mma.sync.aligned.m16n8k16.row.col.f32.f16.f16.f32 "
        "{%0,%1,%2,%3}, {%4,%5,%6,%7}, {%8,%9}, {%0,%1,%2,%3};"
        : "+f"(d0), "+f"(d1), "+f"(d2), "+f"(d3)
        : "r"(a0), "r"(a1), "r"(a2), "r"(a3), "r"(b0), "r"(b1));
}

__device__ __forceinline__ void ldsm_x4(uint32_t& r0, uint32_t& r1,
                                        uint32_t& r2, uint32_t& r3,
                                        const void* p)
{
    uint32_t a = (uint32_t)__cvta_generic_to_shared(p);
    asm volatile(
        "ldmatrix.sync.aligned.m8n8.x4.shared.b16 {%0,%1,%2,%3}, [%4];"
        : "=r"(r0), "=r"(r1), "=r"(r2), "=r"(r3) : "r"(a));
}

__device__ __forceinline__ void ldsm_x4_trans(uint32_t& r0, uint32_t& r1,
                                              uint32_t& r2, uint32_t& r3,
                                              const void* p)
{
    uint32_t a = (uint32_t)__cvta_generic_to_shared(p);
    asm volatile(
        "ldmatrix.sync.aligned.m8n8.x4.trans.shared.b16 {%0,%1,%2,%3}, [%4];"
        : "=r"(r0), "=r"(r1), "=r"(r2), "=r"(r3) : "r"(a));
}

__device__ __forceinline__ void cp16(void* smem, const void* gmem)
{
    uint32_t a = (uint32_t)__cvta_generic_to_shared(smem);
    asm volatile("cp.async.cg.shared.global [%0], [%1], 16;"
                 :: "r"(a), "l"(gmem));
}

__device__ __forceinline__ uint32_t exp2_f16x2(float t0, float t1)
{
    uint32_t p;
    asm("cvt.rn.f16x2.f32 %0, %1, %2;" : "=r"(p) : "f"(t1), "f"(t0));
    asm("ex2.approx.f16x2 %0, %0;" : "+r"(p));
    return p;
}

// ---------------------------------------------------------------------------
// Kernel 1: grouped 1x1 conv as HMMA GEMM. CTA = (l-tile 256, bh).
// Out[l][o] = sum_c X[c][l] * W[o][c] ; PE (sincos) fused into K epilogue.
// ---------------------------------------------------------------------------
__global__ __launch_bounds__(256) void qkv_kernel(
    const float* __restrict__ x,
    const float* __restrict__ wq,
    const float* __restrict__ wk,
    const float* __restrict__ wv)
{
    __shared__ __half Xs[32][XPAD];      // [c][l]
    __shared__ __half Ws[3][32][WPAD];   // [mat][o][c]

    const int l0  = blockIdx.x * XLT;
    const int bh  = blockIdx.y;
    const int b   = bh >> 3;
    const int h   = bh & 7;
    const int tid = threadIdx.x;
    const int wid = tid >> 5;
    const int lane = tid & 31;
    const int gid = lane >> 2;
    const int tig = lane & 3;

    // stage x tile [32 c][256 l] as fp16
    for (int idx = tid; idx < 32 * 64; idx += 256) {
        const int c  = idx >> 6;
        const int l4 = (idx & 63) * 4;
        const float4 v = *(const float4*)(x +
            ((size_t)(b * CIN + h * 32 + c) * LSP) + l0 + l4);
        __half2 h0 = __floats2half2_rn(v.x, v.y);
        __half2 h1 = __floats2half2_rn(v.z, v.w);
        *(__half2*)&Xs[c][l4]     = h0;
        *(__half2*)&Xs[c][l4 + 2] = h1;
    }
    // stage weights (3 x 32x32) as fp16
    {
        const float* wp[3] = {wq, wk, wv};
        for (int idx = tid; idx < 3072; idx += 256) {
            const int mat = idx >> 10;
            const int o   = (idx >> 5) & 31;
            const int c   = idx & 31;
            Ws[mat][o][c] = __float2half(wp[mat][(h * 32 + o) * 32 + c]);
        }
    }
    __syncthreads();

    const int krow = lane & 7;
    const int kcol = ((lane >> 3) & 3) * 8;
    const int arow_g = ((lane >> 4) << 3) + (lane & 7);
    const int acol_g = ((lane >> 3) & 1) * 8;

    // PE divisors per n-chunk (ch even = h*32 + nc*8 + tig*2)
    float divs[4];
    #pragma unroll
    for (int nc = 0; nc < 4; nc++)
        divs[nc] = __expf(-0.03597789207803197f *
                          (float)(h * 32 + nc * 8 + tig * 2));

    const int m0 = wid * 32;

    #pragma unroll
    for (int mc = 0; mc < 2; mc++) {
        const int m = m0 + mc * 16;
        uint32_t a[2][4];
        #pragma unroll
        for (int ks = 0; ks < 2; ks++)
            ldsm_x4_trans(a[ks][0], a[ks][1], a[ks][2], a[ks][3],
                          &Xs[ks * 16 + arow_g][m + acol_g]);

        #pragma unroll
        for (int mat = 0; mat < 3; mat++) {
            #pragma unroll
            for (int nc = 0; nc < 4; nc++) {
                uint32_t b0, b1, b2, b3;
                ldsm_x4(b0, b1, b2, b3, &Ws[mat][nc * 8 + krow][kcol]);
                float d0 = 0.f, d1 = 0.f, d2 = 0.f, d3 = 0.f;
                mma16816(d0, d1, d2, d3,
                         a[0][0], a[0][1], a[0][2], a[0][3], b0, b1);
                mma16816(d0, d1, d2, d3,
                         a[1][0], a[1][1], a[1][2], a[1][3], b2, b3);

                const int lrow = l0 + m + gid;      // fragment rows: lrow, lrow+8
                const int dch  = nc * 8 + tig * 2;  // cols: dch, dch+1

                if (mat == 0) {
                    __half2 v0 = __floats2half2_rn(d0, d1);
                    __half2 v1 = __floats2half2_rn(d2, d3);
                    *(__half2*)(g_qh + ((size_t)bh * LSP + lrow)     * DH + dch) = v0;
                    *(__half2*)(g_qh + ((size_t)bh * LSP + lrow + 8) * DH + dch) = v1;
                } else if (mat == 1) {
                    float s0, c0, s1, c1;
                    __sincosf(divs[nc] * (float)lrow,       &s0, &c0);
                    __sincosf(divs[nc] * (float)(lrow + 8), &s1, &c1);
                    __half2 v0 = __floats2half2_rn(d0 + s0, d1 + c0);
                    __half2 v1 = __floats2half2_rn(d2 + s1, d3 + c1);
                    *(__half2*)(g_kh + ((size_t)bh * LSP + lrow)     * DH + dch) = v0;
                    *(__half2*)(g_kh + ((size_t)bh * LSP + lrow + 8) * DH + dch) = v1;
                } else {
                    __half* vb = g_vh + (size_t)bh * DH * LSP;
                    vb[(size_t)(dch    ) * LSP + lrow    ] = __float2half(d0);
                    vb[(size_t)(dch + 1) * LSP + lrow    ] = __float2half(d1);
                    vb[(size_t)(dch    ) * LSP + lrow + 8] = __float2half(d2);
                    vb[(size_t)(dch + 1) * LSP + lrow + 8] = __float2half(d3);
                }
            }
        }
    }
}

// ---------------------------------------------------------------------------
// Kernel 2: register-fragment flash attention, HMMA + LDSM + cp.async.
// R7 structure + scalar lsum (deferred quad reduction) + tree max.
// ---------------------------------------------------------------------------
__global__ __launch_bounds__(256, 2) void attn_kernel(float* __restrict__ out)
{
    __shared__ __half Ks[2][KTL][KPAD];   // [buf][key][d]
    __shared__ __half Vs[2][DH][VPAD];    // [buf][d][key]

    const int tid  = threadIdx.x;
    const int wid  = tid >> 5;
    const int lane = tid & 31;
    const int gid  = lane >> 2;
    const int tig  = lane & 3;
    const int bh   = blockIdx.y;
    const int q0   = blockIdx.x * QT + wid * 16;
    const float L2E = 1.4426950408889634f;

    const __half* kbase = g_kh + (size_t)bh * LSP * DH;
    const __half* vbase = g_vh + (size_t)bh * DH * LSP;

    const int kr = tid >> 1, kc = (tid & 1) * 16;
    const int vr0 = tid >> 4,         vc0 = (tid & 15) * 8;
    const int vr1 = (tid + 256) >> 4, vc1 = ((tid + 256) & 15) * 8;

    uint32_t qa[8];
    {
        const __half* qb = g_qh + ((size_t)bh * LSP + q0) * DH;
        #pragma unroll
        for (int kk = 0; kk < 2; kk++) {
            qa[kk*4+0] = *(const uint32_t*)(qb + (gid    ) * DH + kk*16     + tig*2);
            qa[kk*4+1] = *(const uint32_t*)(qb + (gid + 8) * DH + kk*16     + tig*2);
            qa[kk*4+2] = *(const uint32_t*)(qb + (gid    ) * DH + kk*16 + 8 + tig*2);
            qa[kk*4+3] = *(const uint32_t*)(qb + (gid + 8) * DH + kk*16 + 8 + tig*2);
        }
    }

    {
        cp16(&Ks[0][kr][kc],     kbase + (size_t)kr * DH + kc);
        cp16(&Ks[0][kr][kc + 8], kbase + (size_t)kr * DH + kc + 8);
        cp16(&Vs[0][vr0][vc0],   vbase + (size_t)vr0 * LSP + vc0);
        cp16(&Vs[0][vr1][vc1],   vbase + (size_t)vr1 * LSP + vc1);
        asm volatile("cp.async.commit_group;" ::: "memory");
    }

    float o[16];
    #pragma unroll
    for (int i = 0; i < 16; i++) o[i] = 0.f;
    float m0 = -1e30f, m1 = -1e30f, l0 = 0.f, l1 = 0.f;

    const int krow = lane & 7;
    const int kcol = ((lane >> 3) & 3) * 8;

    for (int kt = 0; kt < NKT; kt++) {
        const int buf = kt & 1;
        if (kt + 1 < NKT) {
            const size_t koff = (size_t)(kt + 1) * KTL;
            cp16(&Ks[buf^1][kr][kc],     kbase + (koff + kr) * DH + kc);
            cp16(&Ks[buf^1][kr][kc + 8], kbase + (koff + kr) * DH + kc + 8);
            cp16(&Vs[buf^1][vr0][vc0],   vbase + (size_t)vr0 * LSP + koff + vc0);
            cp16(&Vs[buf^1][vr1][vc1],   vbase + (size_t)vr1 * LSP + koff + vc1);
            asm volatile("cp.async.commit_group;" ::: "memory");
            asm volatile("cp.async.wait_group 1;" ::: "memory");
        } else {
            asm volatile("cp.async.wait_group 0;" ::: "memory");
        }
        __syncthreads();

        // ---- S = Q x K^T ----
        float s[16][4];
        #pragma unroll
        for (int j = 0; j < 16; j++) {
            uint32_t b0, b1, b2, b3;
            ldsm_x4(b0, b1, b2, b3, &Ks[buf][j * 8 + krow][kcol]);
            s[j][0] = s[j][1] = s[j][2] = s[j][3] = 0.f;
            mma16816(s[j][0], s[j][1], s[j][2], s[j][3],
                     qa[0], qa[1], qa[2], qa[3], b0, b1);
            mma16816(s[j][0], s[j][1], s[j][2], s[j][3],
                     qa[4], qa[5], qa[6], qa[7], b2, b3);
        }

        // ---- row max: tree reduction ----
        float r0[8], r1[8];
        #pragma unroll
        for (int j = 0; j < 8; j++) {
            r0[j] = fmaxf(fmaxf(s[2*j][0], s[2*j][1]),
                          fmaxf(s[2*j+1][0], s[2*j+1][1]));
            r1[j] = fmaxf(fmaxf(s[2*j][2], s[2*j][3]),
                          fmaxf(s[2*j+1][2], s[2*j+1][3]));
        }
        #pragma unroll
        for (int w = 4; w >= 1; w >>= 1) {
            #pragma unroll
            for (int j = 0; j < w; j++) {
                r0[j] = fmaxf(r0[j], r0[j + w]);
                r1[j] = fmaxf(r1[j], r1[j + w]);
            }
        }
        float nm0 = fmaxf(m0, r0[0]);
        float nm1 = fmaxf(m1, r1[0]);
        nm0 = fmaxf(nm0, __shfl_xor_sync(0xffffffffu, nm0, 1));
        nm0 = fmaxf(nm0, __shfl_xor_sync(0xffffffffu, nm0, 2));
        nm1 = fmaxf(nm1, __shfl_xor_sync(0xffffffffu, nm1, 1));
        nm1 = fmaxf(nm1, __shfl_xor_sync(0xffffffffu, nm1, 2));
        const float c0 = __expf(m0 - nm0);
        const float c1 = __expf(m1 - nm1);
        m0 = nm0; m1 = nm1;
        l0 *= c0;  l1 *= c1;
        #pragma unroll
        for (int nc = 0; nc < 4; nc++) {
            o[nc*4+0] *= c0; o[nc*4+1] *= c0;
            o[nc*4+2] *= c1; o[nc*4+3] *= c1;
        }

        // ---- P = exp2((s-m)*log2e), packed; per-thread partial lsum ----
        // (covers cols {tig*2,tig*2+1} of each 8-block; quad-reduced after
        //  the tile loop — valid since m is quad-uniform)
        const float nb0 = -m0 * L2E;
        const float nb1 = -m1 * L2E;
        float lsA0 = 0.f, lsA1 = 0.f, lsB0 = 0.f, lsB1 = 0.f;
        #pragma unroll
        for (int j = 0; j < 16; j++) {
            float t00 = fmaf(s[j][0], L2E, nb0);
            float t01 = fmaf(s[j][1], L2E, nb0);
            float t10 = fmaf(s[j][2], L2E, nb1);
            float t11 = fmaf(s[j][3], L2E, nb1);
            uint32_t p0 = exp2_f16x2(t00, t01);
            uint32_t p1 = exp2_f16x2(t10, t11);
            s[j][0] = __uint_as_float(p0);
            s[j][1] = __uint_as_float(p1);
            float2 f0 = __half22float2(*(__half2*)&p0);
            float2 f1 = __half22float2(*(__half2*)&p1);
            if (j & 1) { lsA1 += f0.x + f0.y; lsB1 += f1.x + f1.y; }
            else       { lsA0 += f0.x + f0.y; lsB0 += f1.x + f1.y; }
        }
        l0 += lsA0 + lsA1;
        l1 += lsB0 + lsB1;

        // ---- O += P x V : nc outer (R7 order, low register pressure) ----
        #pragma unroll
        for (int nc = 0; nc < 4; nc++) {
            float& d0 = o[nc*4+0];
            float& d1 = o[nc*4+1];
            float& d2 = o[nc*4+2];
            float& d3 = o[nc*4+3];
            #pragma unroll
            for (int cc = 0; cc < 4; cc++) {
                uint32_t v0, v1, v2, v3;
                ldsm_x4(v0, v1, v2, v3, &Vs[buf][nc * 8 + krow][cc * 32 + kcol]);
                const int c = cc * 2;
                mma16816(d0, d1, d2, d3,
                         __float_as_uint(s[2*c    ][0]),
                         __float_as_uint(s[2*c    ][1]),
                         __float_as_uint(s[2*c + 1][0]),
                         __float_as_uint(s[2*c + 1][1]),
                         v0, v1);
                mma16816(d0, d1, d2, d3,
                         __float_as_uint(s[2*c + 2][0]),
                         __float_as_uint(s[2*c + 2][1]),
                         __float_as_uint(s[2*c + 3][0]),
                         __float_as_uint(s[2*c + 3][1]),
                         v2, v3);
            }
        }
        __syncthreads();
    }

    // quad reduction of the partial row sums (cols were split across tig)
    l0 += __shfl_xor_sync(0xffffffffu, l0, 1);
    l0 += __shfl_xor_sync(0xffffffffu, l0, 2);
    l1 += __shfl_xor_sync(0xffffffffu, l1, 1);
    l1 += __shfl_xor_sync(0xffffffffu, l1, 2);

    const float inv0 = 1.0f / l0;
    const float inv1 = 1.0f / l1;

    float* ob = out + (size_t)bh * DH * LSP;
    #pragma unroll
    for (int nc = 0; nc < 4; nc++) {
        const int d = nc * 8 + tig * 2;
        ob[(size_t)(d    ) * LSP + q0 + gid    ] = o[nc*4+0] * inv0;
        ob[(size_t)(d + 1) * LSP + q0 + gid    ] = o[nc*4+1] * inv0;
        ob[(size_t)(d    ) * LSP + q0 + gid + 8] = o[nc*4+2] * inv1;
        ob[(size_t)(d + 1) * LSP + q0 + gid + 8] = o[nc*4+3] * inv1;
    }
}

// ---------------------------------------------------------------------------
extern "C" void kernel_launch(void* const* d_in, const int* in_sizes, int n_in,
                              void* d_out, int out_size)
{
    const float* x  = (const float*)d_in[0];
    const float* wq = (const float*)d_in[1];
    const float* wk = (const float*)d_in[2];
    const float* wv = (const float*)d_in[3];
    float* out = (float*)d_out;

    dim3 g1(LSP / XLT, BH_N);
    qkv_kernel<<<g1, 256>>>(x, wq, wk, wv);

    dim3 g2(LSP / QT, BH_N);
    attn_kernel<<<g2, 256>>>(out);
}

// round 11
// speedup vs baseline: 1.1327x; 1.0620x over previous
#include <cuda_runtime.h>
#include <cuda_fp16.h>
#include <cstdint>

#define BATCH 16
#define HEADS 8
#define DH 32
#define LSP 1024
#define CIN 256
#define BH_N (BATCH*HEADS)
#define QT 128            // queries per CTA in attn (8 warps x 16)
#define KTL 128           // keys per tile
#define NKT (LSP/KTL)
#define KPAD 40           // K smem row stride (halves)
#define VPAD 136          // V smem row stride (halves)
#define XLT 256           // l-tile for qkv GEMM
#define XPAD 264          // Xs row stride (halves)
#define WPAD 40           // Ws row stride (halves)

// fp16 staging: q,k as [bh][l][d]; v as [bh][d][l]
__device__ __half g_qh[(size_t)BH_N * LSP * DH];
__device__ __half g_kh[(size_t)BH_N * LSP * DH];
__device__ __half g_vh[(size_t)BH_N * DH * LSP];

// ---------------------------------------------------------------------------
// HMMA / LDSM / cp.async helpers
// ---------------------------------------------------------------------------
__device__ __forceinline__ void mma16816(
    float& d0, float& d1, float& d2, float& d3,
    uint32_t a0, uint32_t a1, uint32_t a2, uint32_t a3,
    uint32_t b0, uint32_t b1)
{
    asm volatile(
        "mma.sync.aligned.m16n8k16.row.col.f32.f16.f16.f32 "
        "{%0,%1,%2,%3}, {%4,%5,%6,%7}, {%8,%9}, {%0,%1,%2,%3};"
        : "+f"(d0), "+f"(d1), "+f"(d2), "+f"(d3)
        : "r"(a0), "r"(a1), "r"(a2), "r"(a3), "r"(b0), "r"(b1));
}

__device__ __forceinline__ void ldsm_x4(uint32_t& r0, uint32_t& r1,
                                        uint32_t& r2, uint32_t& r3,
                                        const void* p)
{
    uint32_t a = (uint32_t)__cvta_generic_to_shared(p);
    asm volatile(
        "ldmatrix.sync.aligned.m8n8.x4.shared.b16 {%0,%1,%2,%3}, [%4];"
        : "=r"(r0), "=r"(r1), "=r"(r2), "=r"(r3) : "r"(a));
}

__device__ __forceinline__ void ldsm_x4_trans(uint32_t& r0, uint32_t& r1,
                                              uint32_t& r2, uint32_t& r3,
                                              const void* p)
{
    uint32_t a = (uint32_t)__cvta_generic_to_shared(p);
    asm volatile(
        "ldmatrix.sync.aligned.m8n8.x4.trans.shared.b16 {%0,%1,%2,%3}, [%4];"
        : "=r"(r0), "=r"(r1), "=r"(r2), "=r"(r3) : "r"(a));
}

__device__ __forceinline__ void cp16(void* smem, const void* gmem)
{
    uint32_t a = (uint32_t)__cvta_generic_to_shared(smem);
    asm volatile("cp.async.cg.shared.global [%0], [%1], 16;"
                 :: "r"(a), "l"(gmem));
}

__device__ __forceinline__ uint32_t exp2_f16x2(float t0, float t1)
{
    uint32_t p;
    asm("cvt.rn.f16x2.f32 %0, %1, %2;" : "=r"(p) : "f"(t1), "f"(t0));
    asm("ex2.approx.f16x2 %0, %0;" : "+r"(p));
    return p;
}

// ---------------------------------------------------------------------------
// Kernel 1: grouped 1x1 conv as HMMA GEMM (unchanged, proven ~17us).
// ---------------------------------------------------------------------------
__global__ __launch_bounds__(256) void qkv_kernel(
    const float* __restrict__ x,
    const float* __restrict__ wq,
    const float* __restrict__ wk,
    const float* __restrict__ wv)
{
    __shared__ __half Xs[32][XPAD];      // [c][l]
    __shared__ __half Ws[3][32][WPAD];   // [mat][o][c]

    const int l0  = blockIdx.x * XLT;
    const int bh  = blockIdx.y;
    const int b   = bh >> 3;
    const int h   = bh & 7;
    const int tid = threadIdx.x;
    const int wid = tid >> 5;
    const int lane = tid & 31;
    const int gid = lane >> 2;
    const int tig = lane & 3;

    for (int idx = tid; idx < 32 * 64; idx += 256) {
        const int c  = idx >> 6;
        const int l4 = (idx & 63) * 4;
        const float4 v = *(const float4*)(x +
            ((size_t)(b * CIN + h * 32 + c) * LSP) + l0 + l4);
        __half2 h0 = __floats2half2_rn(v.x, v.y);
        __half2 h1 = __floats2half2_rn(v.z, v.w);
        *(__half2*)&Xs[c][l4]     = h0;
        *(__half2*)&Xs[c][l4 + 2] = h1;
    }
    {
        const float* wp[3] = {wq, wk, wv};
        for (int idx = tid; idx < 3072; idx += 256) {
            const int mat = idx >> 10;
            const int o   = (idx >> 5) & 31;
            const int c   = idx & 31;
            Ws[mat][o][c] = __float2half(wp[mat][(h * 32 + o) * 32 + c]);
        }
    }
    __syncthreads();

    const int krow = lane & 7;
    const int kcol = ((lane >> 3) & 3) * 8;
    const int arow_g = ((lane >> 4) << 3) + (lane & 7);
    const int acol_g = ((lane >> 3) & 1) * 8;

    float divs[4];
    #pragma unroll
    for (int nc = 0; nc < 4; nc++)
        divs[nc] = __expf(-0.03597789207803197f *
                          (float)(h * 32 + nc * 8 + tig * 2));

    const int m0 = wid * 32;

    #pragma unroll
    for (int mc = 0; mc < 2; mc++) {
        const int m = m0 + mc * 16;
        uint32_t a[2][4];
        #pragma unroll
        for (int ks = 0; ks < 2; ks++)
            ldsm_x4_trans(a[ks][0], a[ks][1], a[ks][2], a[ks][3],
                          &Xs[ks * 16 + arow_g][m + acol_g]);

        #pragma unroll
        for (int mat = 0; mat < 3; mat++) {
            #pragma unroll
            for (int nc = 0; nc < 4; nc++) {
                uint32_t b0, b1, b2, b3;
                ldsm_x4(b0, b1, b2, b3, &Ws[mat][nc * 8 + krow][kcol]);
                float d0 = 0.f, d1 = 0.f, d2 = 0.f, d3 = 0.f;
                mma16816(d0, d1, d2, d3,
                         a[0][0], a[0][1], a[0][2], a[0][3], b0, b1);
                mma16816(d0, d1, d2, d3,
                         a[1][0], a[1][1], a[1][2], a[1][3], b2, b3);

                const int lrow = l0 + m + gid;
                const int dch  = nc * 8 + tig * 2;

                if (mat == 0) {
                    __half2 v0 = __floats2half2_rn(d0, d1);
                    __half2 v1 = __floats2half2_rn(d2, d3);
                    *(__half2*)(g_qh + ((size_t)bh * LSP + lrow)     * DH + dch) = v0;
                    *(__half2*)(g_qh + ((size_t)bh * LSP + lrow + 8) * DH + dch) = v1;
                } else if (mat == 1) {
                    float s0, c0, s1, c1;
                    __sincosf(divs[nc] * (float)lrow,       &s0, &c0);
                    __sincosf(divs[nc] * (float)(lrow + 8), &s1, &c1);
                    __half2 v0 = __floats2half2_rn(d0 + s0, d1 + c0);
                    __half2 v1 = __floats2half2_rn(d2 + s1, d3 + c1);
                    *(__half2*)(g_kh + ((size_t)bh * LSP + lrow)     * DH + dch) = v0;
                    *(__half2*)(g_kh + ((size_t)bh * LSP + lrow + 8) * DH + dch) = v1;
                } else {
                    __half* vb = g_vh + (size_t)bh * DH * LSP;
                    vb[(size_t)(dch    ) * LSP + lrow    ] = __float2half(d0);
                    vb[(size_t)(dch + 1) * LSP + lrow    ] = __float2half(d1);
                    vb[(size_t)(dch    ) * LSP + lrow + 8] = __float2half(d2);
                    vb[(size_t)(dch + 1) * LSP + lrow + 8] = __float2half(d3);
                }
            }
        }
    }
}

// ---------------------------------------------------------------------------
// Kernel 2: flash attention. Triple-buffered cp.async (1 sync/tile),
// two independent 64-key online-softmax steps per tile (PV_A overlaps
// softmax_B), lsum via ones-MMA (tensor pipe).
// ---------------------------------------------------------------------------
__global__ __launch_bounds__(256, 2) void attn_kernel(float* __restrict__ out)
{
    __shared__ __half Ks[3][KTL][KPAD];   // [buf][key][d]
    __shared__ __half Vs[3][DH][VPAD];    // [buf][d][key]

    const int tid  = threadIdx.x;
    const int wid  = tid >> 5;
    const int lane = tid & 31;
    const int gid  = lane >> 2;
    const int tig  = lane & 3;
    const int bh   = blockIdx.y;
    const int q0   = blockIdx.x * QT + wid * 16;
    const uint32_t ONE2 = 0x3C003C00u;
    const float L2E = 1.4426950408889634f;

    const __half* kbase = g_kh + (size_t)bh * LSP * DH;
    const __half* vbase = g_vh + (size_t)bh * DH * LSP;

    const int kr = tid >> 1, kc = (tid & 1) * 16;
    const int vr0 = tid >> 4,         vc0 = (tid & 15) * 8;
    const int vr1 = (tid + 256) >> 4, vc1 = ((tid + 256) & 15) * 8;

    uint32_t qa[8];
    {
        const __half* qb = g_qh + ((size_t)bh * LSP + q0) * DH;
        #pragma unroll
        for (int kk = 0; kk < 2; kk++) {
            qa[kk*4+0] = *(const uint32_t*)(qb + (gid    ) * DH + kk*16     + tig*2);
            qa[kk*4+1] = *(const uint32_t*)(qb + (gid + 8) * DH + kk*16     + tig*2);
            qa[kk*4+2] = *(const uint32_t*)(qb + (gid    ) * DH + kk*16 + 8 + tig*2);
            qa[kk*4+3] = *(const uint32_t*)(qb + (gid + 8) * DH + kk*16 + 8 + tig*2);
        }
    }

    // prefetch tiles 0 and 1 into buffers 0 and 1
    #pragma unroll
    for (int t = 0; t < 2; t++) {
        const size_t koff = (size_t)t * KTL;
        cp16(&Ks[t][kr][kc],     kbase + (koff + kr) * DH + kc);
        cp16(&Ks[t][kr][kc + 8], kbase + (koff + kr) * DH + kc + 8);
        cp16(&Vs[t][vr0][vc0],   vbase + (size_t)vr0 * LSP + koff + vc0);
        cp16(&Vs[t][vr1][vc1],   vbase + (size_t)vr1 * LSP + koff + vc1);
        asm volatile("cp.async.commit_group;" ::: "memory");
    }

    float o[16];
    #pragma unroll
    for (int i = 0; i < 16; i++) o[i] = 0.f;
    float m0 = -1e30f, m1 = -1e30f, l0 = 0.f, l1 = 0.f;

    const int krow = lane & 7;
    const int kcol = ((lane >> 3) & 3) * 8;

    for (int kt = 0; kt < NKT; kt++) {
        const int buf = kt % 3;
        // wait for tile kt (allow the next one to stay pending)
        if (kt + 1 < NKT) {
            asm volatile("cp.async.wait_group 1;" ::: "memory");
        } else {
            asm volatile("cp.async.wait_group 0;" ::: "memory");
        }
        __syncthreads();
        // prefetch tile kt+2 AFTER the barrier (all warps done with this buf)
        if (kt + 2 < NKT) {
            const int nb = (kt + 2) % 3;
            const size_t koff = (size_t)(kt + 2) * KTL;
            cp16(&Ks[nb][kr][kc],     kbase + (koff + kr) * DH + kc);
            cp16(&Ks[nb][kr][kc + 8], kbase + (koff + kr) * DH + kc + 8);
            cp16(&Vs[nb][vr0][vc0],   vbase + (size_t)vr0 * LSP + koff + vc0);
            cp16(&Vs[nb][vr1][vc1],   vbase + (size_t)vr1 * LSP + koff + vc1);
            asm volatile("cp.async.commit_group;" ::: "memory");
        }

        // ---- S = Q x K^T for the whole 128-key tile ----
        float s[16][4];
        #pragma unroll
        for (int j = 0; j < 16; j++) {
            uint32_t b0, b1, b2, b3;
            ldsm_x4(b0, b1, b2, b3, &Ks[buf][j * 8 + krow][kcol]);
            s[j][0] = s[j][1] = s[j][2] = s[j][3] = 0.f;
            mma16816(s[j][0], s[j][1], s[j][2], s[j][3],
                     qa[0], qa[1], qa[2], qa[3], b0, b1);
            mma16816(s[j][0], s[j][1], s[j][2], s[j][3],
                     qa[4], qa[5], qa[6], qa[7], b2, b3);
        }

        // ---- two independent 64-key online-softmax + PV steps ----
        #pragma unroll
        for (int half = 0; half < 2; half++) {
            const int jb = half * 8;     // fragment base
            // max over this half (tree)
            float r0[4], r1[4];
            #pragma unroll
            for (int j = 0; j < 4; j++) {
                r0[j] = fmaxf(fmaxf(s[jb+2*j][0], s[jb+2*j][1]),
                              fmaxf(s[jb+2*j+1][0], s[jb+2*j+1][1]));
                r1[j] = fmaxf(fmaxf(s[jb+2*j][2], s[jb+2*j][3]),
                              fmaxf(s[jb+2*j+1][2], s[jb+2*j+1][3]));
            }
            r0[0] = fmaxf(fmaxf(r0[0], r0[1]), fmaxf(r0[2], r0[3]));
            r1[0] = fmaxf(fmaxf(r1[0], r1[1]), fmaxf(r1[2], r1[3]));
            float nm0 = fmaxf(m0, r0[0]);
            float nm1 = fmaxf(m1, r1[0]);
            nm0 = fmaxf(nm0, __shfl_xor_sync(0xffffffffu, nm0, 1));
            nm0 = fmaxf(nm0, __shfl_xor_sync(0xffffffffu, nm0, 2));
            nm1 = fmaxf(nm1, __shfl_xor_sync(0xffffffffu, nm1, 1));
            nm1 = fmaxf(nm1, __shfl_xor_sync(0xffffffffu, nm1, 2));
            const float c0 = __expf(m0 - nm0);
            const float c1 = __expf(m1 - nm1);
            m0 = nm0; m1 = nm1;
            l0 *= c0;  l1 *= c1;
            #pragma unroll
            for (int nc = 0; nc < 4; nc++) {
                o[nc*4+0] *= c0; o[nc*4+1] *= c0;
                o[nc*4+2] *= c1; o[nc*4+3] *= c1;
            }

            // exp + pack P in place
            const float nb0 = -m0 * L2E;
            const float nb1 = -m1 * L2E;
            #pragma unroll
            for (int j = jb; j < jb + 8; j++) {
                float t00 = fmaf(s[j][0], L2E, nb0);
                float t01 = fmaf(s[j][1], L2E, nb0);
                float t10 = fmaf(s[j][2], L2E, nb1);
                float t11 = fmaf(s[j][3], L2E, nb1);
                s[j][0] = __uint_as_float(exp2_f16x2(t00, t01));
                s[j][1] = __uint_as_float(exp2_f16x2(t10, t11));
            }

            // lsum for this half = P x ones (4-deep MMA chain, tensor pipe)
            {
                float z0 = 0.f, z1 = 0.f, z2 = 0.f, z3 = 0.f;
                #pragma unroll
                for (int c = 0; c < 4; c++) {
                    mma16816(z0, z1, z2, z3,
                             __float_as_uint(s[jb + 2*c    ][0]),
                             __float_as_uint(s[jb + 2*c    ][1]),
                             __float_as_uint(s[jb + 2*c + 1][0]),
                             __float_as_uint(s[jb + 2*c + 1][1]),
                             ONE2, ONE2);
                }
                l0 += z0;
                l1 += z2;
            }

            // PV for this half: keys jb*8 .. jb*8+63 -> cc = half*2, half*2+1
            #pragma unroll
            for (int nc = 0; nc < 4; nc++) {
                float& d0 = o[nc*4+0];
                float& d1 = o[nc*4+1];
                float& d2 = o[nc*4+2];
                float& d3 = o[nc*4+3];
                #pragma unroll
                for (int ci = 0; ci < 2; ci++) {
                    const int cc = half * 2 + ci;
                    uint32_t v0, v1, v2, v3;
                    ldsm_x4(v0, v1, v2, v3,
                            &Vs[buf][nc * 8 + krow][cc * 32 + kcol]);
                    const int c = jb + ci * 4;
                    mma16816(d0, d1, d2, d3,
                             __float_as_uint(s[c    ][0]),
                             __float_as_uint(s[c    ][1]),
                             __float_as_uint(s[c + 1][0]),
                             __float_as_uint(s[c + 1][1]),
                             v0, v1);
                    mma16816(d0, d1, d2, d3,
                             __float_as_uint(s[c + 2][0]),
                             __float_as_uint(s[c + 2][1]),
                             __float_as_uint(s[c + 3][0]),
                             __float_as_uint(s[c + 3][1]),
                             v2, v3);
                }
            }
        }
    }

    const float inv0 = 1.0f / l0;
    const float inv1 = 1.0f / l1;

    float* ob = out + (size_t)bh * DH * LSP;
    #pragma unroll
    for (int nc = 0; nc < 4; nc++) {
        const int d = nc * 8 + tig * 2;
        ob[(size_t)(d    ) * LSP + q0 + gid    ] = o[nc*4+0] * inv0;
        ob[(size_t)(d + 1) * LSP + q0 + gid    ] = o[nc*4+1] * inv0;
        ob[(size_t)(d    ) * LSP + q0 + gid + 8] = o[nc*4+2] * inv1;
        ob[(size_t)(d + 1) * LSP + q0 + gid + 8] = o[nc*4+3] * inv1;
    }
}

// ---------------------------------------------------------------------------
extern "C" void kernel_launch(void* const* d_in, const int* in_sizes, int n_in,
                              void* d_out, int out_size)
{
    const float* x  = (const float*)d_in[0];
    const float* wq = (const float*)d_in[1];
    const float* wk = (const float*)d_in[2];
    const float* wv = (const float*)d_in[3];
    float* out = (float*)d_out;

    dim3 g1(LSP / XLT, BH_N);
    qkv_kernel<<<g1, 256>>>(x, wq, wk, wv);

    dim3 g2(LSP / QT, BH_N);
    attn_kernel<<<g2, 256>>>(out);
}

// round 12
// speedup vs baseline: 1.1927x; 1.0530x over previous
#include <cuda_runtime.h>
#include <cuda_fp16.h>
#include <cstdint>

#define BATCH 16
#define HEADS 8
#define DH 32
#define LSP 1024
#define CIN 256
#define BH_N (BATCH*HEADS)
#define QT 128            // queries per CTA in attn (8 warps x 16)
#define KTL 128           // keys per tile
#define NKT (LSP/KTL)
#define KPAD 40           // K smem row stride (halves)
#define VPAD 136          // V smem row stride (halves)
#define XLT 256           // l-tile for qkv GEMM
#define XPAD 264          // Xs row stride (halves)
#define WPAD 40           // Ws row stride (halves)
#define VSTP 264          // V transpose-stage row stride (halves)

// fp16 staging: q,k as [bh][l][d]; v as [bh][d][l]
__device__ __half g_qh[(size_t)BH_N * LSP * DH];
__device__ __half g_kh[(size_t)BH_N * LSP * DH];
__device__ __half g_vh[(size_t)BH_N * DH * LSP];

// ---------------------------------------------------------------------------
// HMMA / LDSM / cp.async helpers
// ---------------------------------------------------------------------------
__device__ __forceinline__ void mma16816(
    float& d0, float& d1, float& d2, float& d3,
    uint32_t a0, uint32_t a1, uint32_t a2, uint32_t a3,
    uint32_t b0, uint32_t b1)
{
    asm volatile(
        "mma.sync.aligned.m16n8k16.row.col.f32.f16.f16.f32 "
        "{%0,%1,%2,%3}, {%4,%5,%6,%7}, {%8,%9}, {%0,%1,%2,%3};"
        : "+f"(d0), "+f"(d1), "+f"(d2), "+f"(d3)
        : "r"(a0), "r"(a1), "r"(a2), "r"(a3), "r"(b0), "r"(b1));
}

__device__ __forceinline__ void ldsm_x4(uint32_t& r0, uint32_t& r1,
                                        uint32_t& r2, uint32_t& r3,
                                        const void* p)
{
    uint32_t a = (uint32_t)__cvta_generic_to_shared(p);
    asm volatile(
        "ldmatrix.sync.aligned.m8n8.x4.shared.b16 {%0,%1,%2,%3}, [%4];"
        : "=r"(r0), "=r"(r1), "=r"(r2), "=r"(r3) : "r"(a));
}

__device__ __forceinline__ void ldsm_x4_trans(uint32_t& r0, uint32_t& r1,
                                              uint32_t& r2, uint32_t& r3,
                                              const void* p)
{
    uint32_t a = (uint32_t)__cvta_generic_to_shared(p);
    asm volatile(
        "ldmatrix.sync.aligned.m8n8.x4.trans.shared.b16 {%0,%1,%2,%3}, [%4];"
        : "=r"(r0), "=r"(r1), "=r"(r2), "=r"(r3) : "r"(a));
}

__device__ __forceinline__ void cp16(void* smem, const void* gmem)
{
    uint32_t a = (uint32_t)__cvta_generic_to_shared(smem);
    asm volatile("cp.async.cg.shared.global [%0], [%1], 16;"
                 :: "r"(a), "l"(gmem));
}

__device__ __forceinline__ uint32_t exp2_f16x2(float t0, float t1)
{
    uint32_t p;
    asm("cvt.rn.f16x2.f32 %0, %1, %2;" : "=r"(p) : "f"(t1), "f"(t0));
    asm("ex2.approx.f16x2 %0, %0;" : "+r"(p));
    return p;
}

// ---------------------------------------------------------------------------
// Kernel 1: grouped 1x1 conv as HMMA GEMM. V epilogue now goes through a
// smem transpose stage -> coalesced 16B global stores (was 32 scattered
// 2B STGs per thread).
// ---------------------------------------------------------------------------
__global__ __launch_bounds__(256) void qkv_kernel(
    const float* __restrict__ x,
    const float* __restrict__ wq,
    const float* __restrict__ wk,
    const float* __restrict__ wv)
{
    __shared__ __half Xs[32][XPAD];      // [c][l]
    __shared__ __half Ws[3][32][WPAD];   // [mat][o][c]
    __shared__ __half Vst[32][VSTP];     // [d][l] transpose stage

    const int l0  = blockIdx.x * XLT;
    const int bh  = blockIdx.y;
    const int b   = bh >> 3;
    const int h   = bh & 7;
    const int tid = threadIdx.x;
    const int wid = tid >> 5;
    const int lane = tid & 31;
    const int gid = lane >> 2;
    const int tig = lane & 3;

    for (int idx = tid; idx < 32 * 64; idx += 256) {
        const int c  = idx >> 6;
        const int l4 = (idx & 63) * 4;
        const float4 v = *(const float4*)(x +
            ((size_t)(b * CIN + h * 32 + c) * LSP) + l0 + l4);
        __half2 h0 = __floats2half2_rn(v.x, v.y);
        __half2 h1 = __floats2half2_rn(v.z, v.w);
        *(__half2*)&Xs[c][l4]     = h0;
        *(__half2*)&Xs[c][l4 + 2] = h1;
    }
    {
        const float* wp[3] = {wq, wk, wv};
        for (int idx = tid; idx < 3072; idx += 256) {
            const int mat = idx >> 10;
            const int o   = (idx >> 5) & 31;
            const int c   = idx & 31;
            Ws[mat][o][c] = __float2half(wp[mat][(h * 32 + o) * 32 + c]);
        }
    }
    __syncthreads();

    const int krow = lane & 7;
    const int kcol = ((lane >> 3) & 3) * 8;
    const int arow_g = ((lane >> 4) << 3) + (lane & 7);
    const int acol_g = ((lane >> 3) & 1) * 8;

    float divs[4];
    #pragma unroll
    for (int nc = 0; nc < 4; nc++)
        divs[nc] = __expf(-0.03597789207803197f *
                          (float)(h * 32 + nc * 8 + tig * 2));

    const int m0 = wid * 32;

    #pragma unroll
    for (int mc = 0; mc < 2; mc++) {
        const int m = m0 + mc * 16;
        uint32_t a[2][4];
        #pragma unroll
        for (int ks = 0; ks < 2; ks++)
            ldsm_x4_trans(a[ks][0], a[ks][1], a[ks][2], a[ks][3],
                          &Xs[ks * 16 + arow_g][m + acol_g]);

        #pragma unroll
        for (int mat = 0; mat < 3; mat++) {
            #pragma unroll
            for (int nc = 0; nc < 4; nc++) {
                uint32_t b0, b1, b2, b3;
                ldsm_x4(b0, b1, b2, b3, &Ws[mat][nc * 8 + krow][kcol]);
                float d0 = 0.f, d1 = 0.f, d2 = 0.f, d3 = 0.f;
                mma16816(d0, d1, d2, d3,
                         a[0][0], a[0][1], a[0][2], a[0][3], b0, b1);
                mma16816(d0, d1, d2, d3,
                         a[1][0], a[1][1], a[1][2], a[1][3], b2, b3);

                const int lrow = l0 + m + gid;      // global l
                const int lml  = m + gid;           // local l within tile
                const int dch  = nc * 8 + tig * 2;

                if (mat == 0) {
                    __half2 v0 = __floats2half2_rn(d0, d1);
                    __half2 v1 = __floats2half2_rn(d2, d3);
                    *(__half2*)(g_qh + ((size_t)bh * LSP + lrow)     * DH + dch) = v0;
                    *(__half2*)(g_qh + ((size_t)bh * LSP + lrow + 8) * DH + dch) = v1;
                } else if (mat == 1) {
                    float s0, c0, s1, c1;
                    __sincosf(divs[nc] * (float)lrow,       &s0, &c0);
                    __sincosf(divs[nc] * (float)(lrow + 8), &s1, &c1);
                    __half2 v0 = __floats2half2_rn(d0 + s0, d1 + c0);
                    __half2 v1 = __floats2half2_rn(d2 + s1, d3 + c1);
                    *(__half2*)(g_kh + ((size_t)bh * LSP + lrow)     * DH + dch) = v0;
                    *(__half2*)(g_kh + ((size_t)bh * LSP + lrow + 8) * DH + dch) = v1;
                } else {
                    Vst[dch    ][lml    ] = __float2half(d0);
                    Vst[dch + 1][lml    ] = __float2half(d1);
                    Vst[dch    ][lml + 8] = __float2half(d2);
                    Vst[dch + 1][lml + 8] = __float2half(d3);
                }
            }
        }
    }

    // flush V transpose stage: coalesced 16B stores
    __syncthreads();
    {
        __half* vb = g_vh + (size_t)bh * DH * LSP + l0;
        #pragma unroll
        for (int i = tid; i < 1024; i += 256) {
            const int d = i >> 5;          // 0..31
            const int ch = (i & 31) * 8;   // half offset within row
            *(uint4*)(vb + (size_t)d * LSP + ch) = *(const uint4*)&Vst[d][ch];
        }
    }
}

// ---------------------------------------------------------------------------
// Kernel 2: flash attention (unchanged from R11 — best attn so far).
// ---------------------------------------------------------------------------
__global__ __launch_bounds__(256, 2) void attn_kernel(float* __restrict__ out)
{
    __shared__ __half Ks[3][KTL][KPAD];   // [buf][key][d]
    __shared__ __half Vs[3][DH][VPAD];    // [buf][d][key]

    const int tid  = threadIdx.x;
    const int wid  = tid >> 5;
    const int lane = tid & 31;
    const int gid  = lane >> 2;
    const int tig  = lane & 3;
    const int bh   = blockIdx.y;
    const int q0   = blockIdx.x * QT + wid * 16;
    const uint32_t ONE2 = 0x3C003C00u;
    const float L2E = 1.4426950408889634f;

    const __half* kbase = g_kh + (size_t)bh * LSP * DH;
    const __half* vbase = g_vh + (size_t)bh * DH * LSP;

    const int kr = tid >> 1, kc = (tid & 1) * 16;
    const int vr0 = tid >> 4,         vc0 = (tid & 15) * 8;
    const int vr1 = (tid + 256) >> 4, vc1 = ((tid + 256) & 15) * 8;

    uint32_t qa[8];
    {
        const __half* qb = g_qh + ((size_t)bh * LSP + q0) * DH;
        #pragma unroll
        for (int kk = 0; kk < 2; kk++) {
            qa[kk*4+0] = *(const uint32_t*)(qb + (gid    ) * DH + kk*16     + tig*2);
            qa[kk*4+1] = *(const uint32_t*)(qb + (gid + 8) * DH + kk*16     + tig*2);
            qa[kk*4+2] = *(const uint32_t*)(qb + (gid    ) * DH + kk*16 + 8 + tig*2);
            qa[kk*4+3] = *(const uint32_t*)(qb + (gid + 8) * DH + kk*16 + 8 + tig*2);
        }
    }

    #pragma unroll
    for (int t = 0; t < 2; t++) {
        const size_t koff = (size_t)t * KTL;
        cp16(&Ks[t][kr][kc],     kbase + (koff + kr) * DH + kc);
        cp16(&Ks[t][kr][kc + 8], kbase + (koff + kr) * DH + kc + 8);
        cp16(&Vs[t][vr0][vc0],   vbase + (size_t)vr0 * LSP + koff + vc0);
        cp16(&Vs[t][vr1][vc1],   vbase + (size_t)vr1 * LSP + koff + vc1);
        asm volatile("cp.async.commit_group;" ::: "memory");
    }

    float o[16];
    #pragma unroll
    for (int i = 0; i < 16; i++) o[i] = 0.f;
    float m0 = -1e30f, m1 = -1e30f, l0 = 0.f, l1 = 0.f;

    const int krow = lane & 7;
    const int kcol = ((lane >> 3) & 3) * 8;

    for (int kt = 0; kt < NKT; kt++) {
        const int buf = kt % 3;
        if (kt + 1 < NKT) {
            asm volatile("cp.async.wait_group 1;" ::: "memory");
        } else {
            asm volatile("cp.async.wait_group 0;" ::: "memory");
        }
        __syncthreads();
        if (kt + 2 < NKT) {
            const int nb = (kt + 2) % 3;
            const size_t koff = (size_t)(kt + 2) * KTL;
            cp16(&Ks[nb][kr][kc],     kbase + (koff + kr) * DH + kc);
            cp16(&Ks[nb][kr][kc + 8], kbase + (koff + kr) * DH + kc + 8);
            cp16(&Vs[nb][vr0][vc0],   vbase + (size_t)vr0 * LSP + koff + vc0);
            cp16(&Vs[nb][vr1][vc1],   vbase + (size_t)vr1 * LSP + koff + vc1);
            asm volatile("cp.async.commit_group;" ::: "memory");
        }

        // ---- S = Q x K^T ----
        float s[16][4];
        #pragma unroll
        for (int j = 0; j < 16; j++) {
            uint32_t b0, b1, b2, b3;
            ldsm_x4(b0, b1, b2, b3, &Ks[buf][j * 8 + krow][kcol]);
            s[j][0] = s[j][1] = s[j][2] = s[j][3] = 0.f;
            mma16816(s[j][0], s[j][1], s[j][2], s[j][3],
                     qa[0], qa[1], qa[2], qa[3], b0, b1);
            mma16816(s[j][0], s[j][1], s[j][2], s[j][3],
                     qa[4], qa[5], qa[6], qa[7], b2, b3);
        }

        // ---- two independent 64-key online-softmax + PV steps ----
        #pragma unroll
        for (int half = 0; half < 2; half++) {
            const int jb = half * 8;
            float r0[4], r1[4];
            #pragma unroll
            for (int j = 0; j < 4; j++) {
                r0[j] = fmaxf(fmaxf(s[jb+2*j][0], s[jb+2*j][1]),
                              fmaxf(s[jb+2*j+1][0], s[jb+2*j+1][1]));
                r1[j] = fmaxf(fmaxf(s[jb+2*j][2], s[jb+2*j][3]),
                              fmaxf(s[jb+2*j+1][2], s[jb+2*j+1][3]));
            }
            r0[0] = fmaxf(fmaxf(r0[0], r0[1]), fmaxf(r0[2], r0[3]));
            r1[0] = fmaxf(fmaxf(r1[0], r1[1]), fmaxf(r1[2], r1[3]));
            float nm0 = fmaxf(m0, r0[0]);
            float nm1 = fmaxf(m1, r1[0]);
            nm0 = fmaxf(nm0, __shfl_xor_sync(0xffffffffu, nm0, 1));
            nm0 = fmaxf(nm0, __shfl_xor_sync(0xffffffffu, nm0, 2));
            nm1 = fmaxf(nm1, __shfl_xor_sync(0xffffffffu, nm1, 1));
            nm1 = fmaxf(nm1, __shfl_xor_sync(0xffffffffu, nm1, 2));
            const float c0 = __expf(m0 - nm0);
            const float c1 = __expf(m1 - nm1);
            m0 = nm0; m1 = nm1;
            l0 *= c0;  l1 *= c1;
            #pragma unroll
            for (int nc = 0; nc < 4; nc++) {
                o[nc*4+0] *= c0; o[nc*4+1] *= c0;
                o[nc*4+2] *= c1; o[nc*4+3] *= c1;
            }

            const float nb0 = -m0 * L2E;
            const float nb1 = -m1 * L2E;
            #pragma unroll
            for (int j = jb; j < jb + 8; j++) {
                float t00 = fmaf(s[j][0], L2E, nb0);
                float t01 = fmaf(s[j][1], L2E, nb0);
                float t10 = fmaf(s[j][2], L2E, nb1);
                float t11 = fmaf(s[j][3], L2E, nb1);
                s[j][0] = __uint_as_float(exp2_f16x2(t00, t01));
                s[j][1] = __uint_as_float(exp2_f16x2(t10, t11));
            }

            {
                float z0 = 0.f, z1 = 0.f, z2 = 0.f, z3 = 0.f;
                #pragma unroll
                for (int c = 0; c < 4; c++) {
                    mma16816(z0, z1, z2, z3,
                             __float_as_uint(s[jb + 2*c    ][0]),
                             __float_as_uint(s[jb + 2*c    ][1]),
                             __float_as_uint(s[jb + 2*c + 1][0]),
                             __float_as_uint(s[jb + 2*c + 1][1]),
                             ONE2, ONE2);
                }
                l0 += z0;
                l1 += z2;
            }

            #pragma unroll
            for (int nc = 0; nc < 4; nc++) {
                float& d0 = o[nc*4+0];
                float& d1 = o[nc*4+1];
                float& d2 = o[nc*4+2];
                float& d3 = o[nc*4+3];
                #pragma unroll
                for (int ci = 0; ci < 2; ci++) {
                    const int cc = half * 2 + ci;
                    uint32_t v0, v1, v2, v3;
                    ldsm_x4(v0, v1, v2, v3,
                            &Vs[buf][nc * 8 + krow][cc * 32 + kcol]);
                    const int c = jb + ci * 4;
                    mma16816(d0, d1, d2, d3,
                             __float_as_uint(s[c    ][0]),
                             __float_as_uint(s[c    ][1]),
                             __float_as_uint(s[c + 1][0]),
                             __float_as_uint(s[c + 1][1]),
                             v0, v1);
                    mma16816(d0, d1, d2, d3,
                             __float_as_uint(s[c + 2][0]),
                             __float_as_uint(s[c + 2][1]),
                             __float_as_uint(s[c + 3][0]),
                             __float_as_uint(s[c + 3][1]),
                             v2, v3);
                }
            }
        }
    }

    const float inv0 = 1.0f / l0;
    const float inv1 = 1.0f / l1;

    float* ob = out + (size_t)bh * DH * LSP;
    #pragma unroll
    for (int nc = 0; nc < 4; nc++) {
        const int d = nc * 8 + tig * 2;
        ob[(size_t)(d    ) * LSP + q0 + gid    ] = o[nc*4+0] * inv0;
        ob[(size_t)(d + 1) * LSP + q0 + gid    ] = o[nc*4+1] * inv0;
        ob[(size_t)(d    ) * LSP + q0 + gid + 8] = o[nc*4+2] * inv1;
        ob[(size_t)(d + 1) * LSP + q0 + gid + 8] = o[nc*4+3] * inv1;
    }
}

// ---------------------------------------------------------------------------
extern "C" void kernel_launch(void* const* d_in, const int* in_sizes, int n_in,
                              void* d_out, int out_size)
{
    const float* x  = (const float*)d_in[0];
    const float* wq = (const float*)d_in[1];
    const float* wk = (const float*)d_in[2];
    const float* wv = (const float*)d_in[3];
    float* out = (float*)d_out;

    dim3 g1(LSP / XLT, BH_N);
    qkv_kernel<<<g1, 256>>>(x, wq, wk, wv);

    dim3 g2(LSP / QT, BH_N);
    attn_kernel<<<g2, 256>>>(out);
}